// round 2
// baseline (speedup 1.0000x reference)
#include <cuda_runtime.h>
#include <mma.h>
#include <math.h>
#include <stdint.h>

using namespace nvcuda;

#define BB   4
#define LL   4096
#define DD   1024
#define FFD  2048
#define CCH  16
#define TT   256      // LL / CCH
#define EPSL 1e-5f

// ---------------- scratch (device globals; no allocations allowed) ----------
__device__ float  g_xn  [(size_t)BB*LL*DD];    // LN(x)
__device__ float  g_conv[(size_t)BB*LL*DD];    // conv real part
__device__ float  g_x3  [(size_t)BB*LL*DD];    // LN(x2)
__device__ float  g_t   [(size_t)BB*LL*FFD];   // silu(x3@w1+b1)
__device__ float2 g_fin [(size_t)BB*CCH*DD];
__device__ float2 g_cry [(size_t)BB*CCH*DD];

// ---------------- LayerNorm: one block per row, D=1024, 256 thr x float4 ----
__global__ __launch_bounds__(256) void ln_kernel(const float* __restrict__ x,
                                                 const float* __restrict__ g,
                                                 const float* __restrict__ bsh,
                                                 float* __restrict__ out) {
    __shared__ float rs[8], rq[8], stats[2];
    const int row = blockIdx.x, t = threadIdx.x;
    const float4* xr = reinterpret_cast<const float4*>(x + (size_t)row * DD);
    float4 v = xr[t];
    float s = v.x + v.y + v.z + v.w;
    float q = fmaf(v.x, v.x, fmaf(v.y, v.y, fmaf(v.z, v.z, v.w * v.w)));
#pragma unroll
    for (int o = 16; o > 0; o >>= 1) {
        s += __shfl_down_sync(0xffffffffu, s, o);
        q += __shfl_down_sync(0xffffffffu, q, o);
    }
    if ((t & 31) == 0) { rs[t >> 5] = s; rq[t >> 5] = q; }
    __syncthreads();
    if (t == 0) {
        float ss = 0.f, qq = 0.f;
#pragma unroll
        for (int i = 0; i < 8; i++) { ss += rs[i]; qq += rq[i]; }
        float mean = ss * (1.0f / DD);
        float var  = qq * (1.0f / DD) - mean * mean;
        stats[0] = mean;
        stats[1] = rsqrtf(var + EPSL);
    }
    __syncthreads();
    const float mean = stats[0], inv = stats[1];
    const float4 gv = reinterpret_cast<const float4*>(g)[t];
    const float4 bv = reinterpret_cast<const float4*>(bsh)[t];
    float4 o;
    o.x = (v.x - mean) * inv * gv.x + bv.x;
    o.y = (v.y - mean) * inv * gv.y + bv.y;
    o.z = (v.z - mean) * inv * gv.z + bv.z;
    o.w = (v.w - mean) * inv * gv.w + bv.w;
    reinterpret_cast<float4*>(out + (size_t)row * DD)[t] = o;
}

// ---------------- spiral conv as chunked complex scan -----------------------
__device__ __forceinline__ void get_phz(const float* __restrict__ phre,
                                        const float* __restrict__ phim,
                                        int d, float& a, float& zr, float& zi) {
    float re = phre[d], im = phim[d];
    a = sqrtf(re * re + im * im);
    float sc = expf(-a) / a;
    zr = re * sc;
    zi = im * sc;
}

// phz^n exactly (fp64 phase), n >= 0
__device__ __forceinline__ void cpow(float zr, float zi, float a, int n,
                                     float& pr, float& pi) {
    double th  = atan2((double)zi, (double)zr);
    double ang = th * (double)n;
    double mg  = exp(-(double)a * (double)n);
    pr = (float)(mg * cos(ang));
    pi = (float)(mg * sin(ang));
}

__global__ __launch_bounds__(256) void conv_a(const float* __restrict__ xn,
                                              const float* __restrict__ phre,
                                              const float* __restrict__ phim) {
    const int d  = blockIdx.x * 256 + threadIdx.x;
    const int ch = blockIdx.y, bb = blockIdx.z;
    float a, zr, zi;
    get_phz(phre, phim, d, a, zr, zi);
    float sr = 0.f, si = 0.f;
    const float* p = xn + ((size_t)bb * LL + (size_t)ch * TT) * DD + d;
#pragma unroll 8
    for (int j = 0; j < TT; j++) {
        float v  = p[(size_t)j * DD];
        float nr = fmaf(zr, sr, fmaf(-zi, si, v));
        float ni = fmaf(zr, si, zi * sr);
        sr = nr; si = ni;
    }
    g_fin[((size_t)bb * CCH + ch) * DD + d] = make_float2(sr, si);
}

__global__ __launch_bounds__(256) void conv_b(const float* __restrict__ phre,
                                              const float* __restrict__ phim) {
    const int idx = blockIdx.x * 256 + threadIdx.x;  // 0..BB*DD-1
    const int d = idx & (DD - 1), bb = idx >> 10;
    float a, zr, zi;
    get_phz(phre, phim, d, a, zr, zi);
    float pr, pi;
    cpow(zr, zi, a, TT, pr, pi);
    float cr = 0.f, ci = 0.f;
#pragma unroll
    for (int c = 0; c < CCH; c++) {
        const size_t o = ((size_t)bb * CCH + c) * DD + d;
        g_cry[o] = make_float2(cr, ci);
        float2 f = g_fin[o];
        float nr = fmaf(pr, cr, fmaf(-pi, ci, f.x));
        float ni = fmaf(pr, ci, fmaf(pi, cr, f.y));
        cr = nr; ci = ni;
    }
}

__global__ __launch_bounds__(256) void conv_c(const float* __restrict__ xn,
                                              const float* __restrict__ phre,
                                              const float* __restrict__ phim,
                                              const float* __restrict__ phire,
                                              const float* __restrict__ phiim,
                                              const float* __restrict__ lcre,
                                              const float* __restrict__ lcim) {
    const int d  = blockIdx.x * 256 + threadIdx.x;
    const int ch = blockIdx.y, bb = blockIdx.z;
    float a, zr, zi;
    get_phz(phre, phim, d, a, zr, zi);
    const float fr = phire[d], fi = phiim[d];
    const float lr = lcre[d],  li = lcim[d];
    const int l0 = ch * TT;
    float br, bi;                      // phz^{l0}
    cpow(zr, zi, a, l0, br, bi);
    const float wr = lr * br - li * bi;   // w = lci * phz^{l0}
    const float wi = lr * bi + li * br;
    float2 cy = g_cry[((size_t)bb * CCH + ch) * DD + d];
    const float cr = cy.x, ci = cy.y;
    float sr = 0.f, si = 0.f;          // local scan
    float qr = 1.f, qi = 0.f;          // phz^{j}; updated to phz^{j+1} first
    const float* p = xn + ((size_t)bb * LL + (size_t)l0) * DD + d;
    float* o = g_conv + ((size_t)bb * LL + (size_t)l0) * DD + d;
#pragma unroll 4
    for (int j = 0; j < TT; j++) {
        float nqr = qr * zr - qi * zi;
        float nqi = qr * zi + qi * zr;
        qr = nqr; qi = nqi;                       // phz^{j+1}
        float v  = p[(size_t)j * DD];
        float nr = fmaf(zr, sr, fmaf(-zi, si, v));
        float ni = fmaf(zr, si, zi * sr);
        sr = nr; si = ni;
        float tr = sr + qr * cr - qi * ci;        // s + phz^{j+1}*carry
        float ti = si + qr * ci + qi * cr;
        o[(size_t)j * DD] = fr * tr - fi * ti + wr * qr - wi * qi;
    }
}

// ---------------- tf32 wmma GEMM, 128x128x32 tiles, fused epilogues ---------
#define EPI_SILU 0
#define EPI_GATE 1
#define EPI_ADD  2

template <int EPI>
__global__ __launch_bounds__(256) void gemm_k(const float* __restrict__ A,
                                              const float* __restrict__ W,
                                              const float* __restrict__ bias,
                                              const float* __restrict__ gate,
                                              const float* __restrict__ resid,
                                              float* __restrict__ out,
                                              int M, int N, int K) {
    __shared__ __align__(16) float As[128 * 36];
    __shared__ __align__(16) float Bs[32 * 132];
    __shared__ __align__(16) float ebuf[8][16 * 20];

    const int tid  = threadIdx.x;
    const int bm0  = blockIdx.y * 128, bn0 = blockIdx.x * 128;
    const int warp = tid >> 5, lane = tid & 31;
    const int wm0  = (warp >> 2) * 64, wn0 = (warp & 3) * 32;

    wmma::fragment<wmma::accumulator, 16, 16, 8, float> acc[4][2];
#pragma unroll
    for (int i = 0; i < 4; i++)
#pragma unroll
        for (int j = 0; j < 2; j++) wmma::fill_fragment(acc[i][j], 0.0f);

    for (int kt = 0; kt < K; kt += 32) {
#pragma unroll
        for (int i = 0; i < 4; i++) {
            int idx = tid + i * 256;
            int r = idx >> 3, c = (idx & 7) << 2;
            float4 v = *reinterpret_cast<const float4*>(A + (size_t)(bm0 + r) * K + kt + c);
            float* dst = As + r * 36 + c;
            dst[0] = wmma::__float_to_tf32(v.x);
            dst[1] = wmma::__float_to_tf32(v.y);
            dst[2] = wmma::__float_to_tf32(v.z);
            dst[3] = wmma::__float_to_tf32(v.w);
        }
#pragma unroll
        for (int i = 0; i < 4; i++) {
            int idx = tid + i * 256;
            int r = idx >> 5, c = (idx & 31) << 2;
            float4 v = *reinterpret_cast<const float4*>(W + (size_t)(kt + r) * N + bn0 + c);
            float* dst = Bs + r * 132 + c;
            dst[0] = wmma::__float_to_tf32(v.x);
            dst[1] = wmma::__float_to_tf32(v.y);
            dst[2] = wmma::__float_to_tf32(v.z);
            dst[3] = wmma::__float_to_tf32(v.w);
        }
        __syncthreads();
#pragma unroll
        for (int kk = 0; kk < 32; kk += 8) {
            wmma::fragment<wmma::matrix_a, 16, 16, 8, wmma::precision::tf32, wmma::row_major> af[4];
            wmma::fragment<wmma::matrix_b, 16, 16, 8, wmma::precision::tf32, wmma::row_major> bf[2];
#pragma unroll
            for (int i = 0; i < 4; i++)
                wmma::load_matrix_sync(af[i], As + (wm0 + i * 16) * 36 + kk, 36);
#pragma unroll
            for (int j = 0; j < 2; j++)
                wmma::load_matrix_sync(bf[j], Bs + kk * 132 + wn0 + j * 16, 132);
#pragma unroll
            for (int i = 0; i < 4; i++)
#pragma unroll
                for (int j = 0; j < 2; j++)
                    wmma::mma_sync(acc[i][j], af[i], bf[j], acc[i][j]);
        }
        __syncthreads();
    }

    const int r = lane >> 1, c0 = (lane & 1) << 3;
#pragma unroll
    for (int i = 0; i < 4; i++) {
#pragma unroll
        for (int j = 0; j < 2; j++) {
            wmma::store_matrix_sync(&ebuf[warp][0], acc[i][j], 20, wmma::mem_row_major);
            __syncwarp();
            const int gr  = bm0 + wm0 + i * 16 + r;
            const int gcb = bn0 + wn0 + j * 16 + c0;
            const size_t go = (size_t)gr * N + gcb;
#pragma unroll
            for (int c = 0; c < 8; c++) {
                float v = ebuf[warp][r * 20 + c0 + c] + bias[gcb + c];
                if (EPI == EPI_SILU) {
                    v = v / (1.0f + expf(-v));
                } else if (EPI == EPI_GATE) {
                    v = v / (1.0f + expf(-v));
                    v = gate[go + c] * v + resid[go + c];
                } else {
                    v = v + resid[go + c];
                }
                out[go + c] = v;
            }
            __syncwarp();
        }
    }
}

// ---------------- launch ----------------------------------------------------
extern "C" void kernel_launch(void* const* d_in, const int* in_sizes, int n_in,
                              void* d_out, int out_size) {
    (void)in_sizes; (void)n_in; (void)out_size;
    const float* x     = (const float*)d_in[0];
    const float* lng   = (const float*)d_in[1];
    const float* lnb   = (const float*)d_in[2];
    const float* fcw   = (const float*)d_in[3];
    const float* fcb   = (const float*)d_in[4];
    const float* w1    = (const float*)d_in[5];
    const float* b1    = (const float*)d_in[6];
    const float* w2    = (const float*)d_in[7];
    const float* b2    = (const float*)d_in[8];
    const float* phre  = (const float*)d_in[9];
    const float* phim  = (const float*)d_in[10];
    const float* phire = (const float*)d_in[11];
    const float* phiim = (const float*)d_in[12];
    const float* lcre  = (const float*)d_in[13];
    const float* lcim  = (const float*)d_in[14];

    float *xn, *conv, *x3, *tb;
    cudaGetSymbolAddress((void**)&xn,   g_xn);
    cudaGetSymbolAddress((void**)&conv, g_conv);
    cudaGetSymbolAddress((void**)&x3,   g_x3);
    cudaGetSymbolAddress((void**)&tb,   g_t);
    float* x2 = (float*)d_out;   // d_out doubles as x2 buffer

    const int M = BB * LL;

    ln_kernel<<<M, 256>>>(x, lng, lnb, xn);
    conv_a<<<dim3(DD / 256, CCH, BB), 256>>>(xn, phre, phim);
    conv_b<<<(BB * DD) / 256, 256>>>(phre, phim);
    conv_c<<<dim3(DD / 256, CCH, BB), 256>>>(xn, phre, phim, phire, phiim, lcre, lcim);

    // x2 = conv * silu(x @ fc_w + fc_b) + x
    gemm_k<EPI_GATE><<<dim3(DD / 128, M / 128), 256>>>(x, fcw, fcb, conv, x, x2, M, DD, DD);
    // x3 = LN(x2)
    ln_kernel<<<M, 256>>>(x2, lng, lnb, x3);
    // t = silu(x3 @ w1 + b1)
    gemm_k<EPI_SILU><<<dim3(FFD / 128, M / 128), 256>>>(x3, w1, b1, nullptr, nullptr, tb, M, FFD, DD);
    // out = x2 + t @ w2 + b2
    gemm_k<EPI_ADD><<<dim3(DD / 128, M / 128), 256>>>(tb, w2, b2, nullptr, x2, x2, M, DD, FFD);
}

// round 3
// speedup vs baseline: 1.2643x; 1.2643x over previous
#include <cuda_runtime.h>
#include <mma.h>
#include <math.h>
#include <stdint.h>

using namespace nvcuda;

#define BB   4
#define LL   4096
#define DD   1024
#define FFD  2048
#define CCH  64
#define TT   64       // LL / CCH
#define EPSL 1e-5f

// ---------------- scratch (device globals; no allocations allowed) ----------
__device__ float  g_xn  [(size_t)BB*LL*DD];    // LN(x)
__device__ float  g_conv[(size_t)BB*LL*DD];    // conv real part
__device__ float  g_x3  [(size_t)BB*LL*DD];    // LN(x2)
__device__ float  g_t   [(size_t)BB*LL*FFD];   // silu(x3@w1+b1)
__device__ float2 g_fin [(size_t)BB*CCH*DD];
__device__ float2 g_cry [(size_t)BB*CCH*DD];

// ---------------- LayerNorm: one block per row, D=1024, 256 thr x float4 ----
__global__ __launch_bounds__(256) void ln_kernel(const float* __restrict__ x,
                                                 const float* __restrict__ g,
                                                 const float* __restrict__ bsh,
                                                 float* __restrict__ out) {
    __shared__ float rs[8], rq[8], stats[2];
    const int row = blockIdx.x, t = threadIdx.x;
    const float4* xr = reinterpret_cast<const float4*>(x + (size_t)row * DD);
    float4 v = xr[t];
    float s = v.x + v.y + v.z + v.w;
    float q = fmaf(v.x, v.x, fmaf(v.y, v.y, fmaf(v.z, v.z, v.w * v.w)));
#pragma unroll
    for (int o = 16; o > 0; o >>= 1) {
        s += __shfl_down_sync(0xffffffffu, s, o);
        q += __shfl_down_sync(0xffffffffu, q, o);
    }
    if ((t & 31) == 0) { rs[t >> 5] = s; rq[t >> 5] = q; }
    __syncthreads();
    if (t == 0) {
        float ss = 0.f, qq = 0.f;
#pragma unroll
        for (int i = 0; i < 8; i++) { ss += rs[i]; qq += rq[i]; }
        float mean = ss * (1.0f / DD);
        float var  = qq * (1.0f / DD) - mean * mean;
        stats[0] = mean;
        stats[1] = rsqrtf(var + EPSL);
    }
    __syncthreads();
    const float mean = stats[0], inv = stats[1];
    const float4 gv = reinterpret_cast<const float4*>(g)[t];
    const float4 bv = reinterpret_cast<const float4*>(bsh)[t];
    float4 o;
    o.x = (v.x - mean) * inv * gv.x + bv.x;
    o.y = (v.y - mean) * inv * gv.y + bv.y;
    o.z = (v.z - mean) * inv * gv.z + bv.z;
    o.w = (v.w - mean) * inv * gv.w + bv.w;
    reinterpret_cast<float4*>(out + (size_t)row * DD)[t] = o;
}

// ---------------- spiral conv as chunked complex scan -----------------------
__device__ __forceinline__ void get_phz(const float* __restrict__ phre,
                                        const float* __restrict__ phim,
                                        int d, float& a, float& zr, float& zi) {
    float re = phre[d], im = phim[d];
    a = sqrtf(re * re + im * im);
    float sc = expf(-a) / a;
    zr = re * sc;
    zi = im * sc;
}

// phz^n exactly (fp64 phase), n >= 0
__device__ __forceinline__ void cpow(float zr, float zi, float a, int n,
                                     float& pr, float& pi) {
    double th  = atan2((double)zi, (double)zr);
    double ang = th * (double)n;
    double mg  = exp(-(double)a * (double)n);
    pr = (float)(mg * cos(ang));
    pi = (float)(mg * sin(ang));
}

__global__ __launch_bounds__(256) void conv_a(const float* __restrict__ xn,
                                              const float* __restrict__ phre,
                                              const float* __restrict__ phim) {
    const int d  = blockIdx.x * 256 + threadIdx.x;
    const int ch = blockIdx.y, bb = blockIdx.z;
    float a, zr, zi;
    get_phz(phre, phim, d, a, zr, zi);
    float sr = 0.f, si = 0.f;
    const float* p = xn + ((size_t)bb * LL + (size_t)ch * TT) * DD + d;
#pragma unroll 8
    for (int j = 0; j < TT; j++) {
        float v  = p[(size_t)j * DD];
        float nr = fmaf(zr, sr, fmaf(-zi, si, v));
        float ni = fmaf(zr, si, zi * sr);
        sr = nr; si = ni;
    }
    g_fin[((size_t)bb * CCH + ch) * DD + d] = make_float2(sr, si);
}

__global__ __launch_bounds__(256) void conv_b(const float* __restrict__ phre,
                                              const float* __restrict__ phim) {
    const int idx = blockIdx.x * 256 + threadIdx.x;  // 0..BB*DD-1
    const int d = idx & (DD - 1), bb = idx >> 10;
    float a, zr, zi;
    get_phz(phre, phim, d, a, zr, zi);
    float pr, pi;
    cpow(zr, zi, a, TT, pr, pi);
    float cr = 0.f, ci = 0.f;
#pragma unroll
    for (int c = 0; c < CCH; c++) {
        const size_t o = ((size_t)bb * CCH + c) * DD + d;
        g_cry[o] = make_float2(cr, ci);
        float2 f = g_fin[o];
        float nr = fmaf(pr, cr, fmaf(-pi, ci, f.x));
        float ni = fmaf(pr, ci, fmaf(pi, cr, f.y));
        cr = nr; ci = ni;
    }
}

__global__ __launch_bounds__(256) void conv_c(const float* __restrict__ xn,
                                              const float* __restrict__ phre,
                                              const float* __restrict__ phim,
                                              const float* __restrict__ phire,
                                              const float* __restrict__ phiim,
                                              const float* __restrict__ lcre,
                                              const float* __restrict__ lcim) {
    const int d  = blockIdx.x * 256 + threadIdx.x;
    const int ch = blockIdx.y, bb = blockIdx.z;
    float a, zr, zi;
    get_phz(phre, phim, d, a, zr, zi);
    const float fr = phire[d], fi = phiim[d];
    const float lr = lcre[d],  li = lcim[d];
    const int l0 = ch * TT;
    float br, bi;                      // phz^{l0}
    cpow(zr, zi, a, l0, br, bi);
    const float wr = lr * br - li * bi;   // w = lci * phz^{l0}
    const float wi = lr * bi + li * br;
    float2 cy = g_cry[((size_t)bb * CCH + ch) * DD + d];
    const float cr = cy.x, ci = cy.y;
    float sr = 0.f, si = 0.f;          // local scan
    float qr = 1.f, qi = 0.f;          // phz^{j}; updated to phz^{j+1} first
    const float* p = xn + ((size_t)bb * LL + (size_t)l0) * DD + d;
    float* o = g_conv + ((size_t)bb * LL + (size_t)l0) * DD + d;
#pragma unroll 8
    for (int j = 0; j < TT; j++) {
        float nqr = qr * zr - qi * zi;
        float nqi = qr * zi + qi * zr;
        qr = nqr; qi = nqi;                       // phz^{j+1}
        float v  = p[(size_t)j * DD];
        float nr = fmaf(zr, sr, fmaf(-zi, si, v));
        float ni = fmaf(zr, si, zi * sr);
        sr = nr; si = ni;
        float tr = sr + qr * cr - qi * ci;        // s + phz^{j+1}*carry
        float ti = si + qr * ci + qi * cr;
        o[(size_t)j * DD] = fr * tr - fi * ti + wr * qr - wi * qi;
    }
}

// ---------------- tf32 wmma GEMM, cp.async 4-stage pipeline ------------------
#define EPI_SILU 0
#define EPI_GATE 1
#define EPI_ADD  2

#define STAGES 4
#define AS_STRIDE 36
#define BS_STRIDE 132
#define STAGE_FLOATS (128 * AS_STRIDE + 32 * BS_STRIDE)   // 8832
#define GEMM_SMEM_BYTES (STAGES * STAGE_FLOATS * 4)       // 141312

__device__ __forceinline__ void cp16(void* dst_smem, const void* src_gmem) {
    uint32_t d = (uint32_t)__cvta_generic_to_shared(dst_smem);
    asm volatile("cp.async.cg.shared.global [%0], [%1], 16;\n" :: "r"(d), "l"(src_gmem));
}

template <int EPI>
__global__ __launch_bounds__(256) void gemm_pipe(const float* __restrict__ A,
                                                 const float* __restrict__ W,
                                                 const float* __restrict__ bias,
                                                 const float* __restrict__ gate,
                                                 const float* __restrict__ resid,
                                                 float* __restrict__ out,
                                                 int M, int N, int K) {
    extern __shared__ float smem[];
    const int tid  = threadIdx.x;
    const int bm0  = blockIdx.y * 128, bn0 = blockIdx.x * 128;
    const int warp = tid >> 5, lane = tid & 31;
    const int wm0  = (warp >> 2) * 64, wn0 = (warp & 3) * 32;
    const int ktiles = K >> 5;

    wmma::fragment<wmma::accumulator, 16, 16, 8, float> acc[4][2];
#pragma unroll
    for (int i = 0; i < 4; i++)
#pragma unroll
        for (int j = 0; j < 2; j++) wmma::fill_fragment(acc[i][j], 0.0f);

    // prologue: stage tiles 0 .. STAGES-2
#pragma unroll
    for (int s = 0; s < STAGES - 1; s++) {
        if (s < ktiles) {
            float* As = smem + s * STAGE_FLOATS;
            float* Bs = As + 128 * AS_STRIDE;
#pragma unroll
            for (int i = 0; i < 4; i++) {
                int idx = tid + i * 256;
                int r = idx >> 3, c = (idx & 7) << 2;
                cp16(As + r * AS_STRIDE + c, A + (size_t)(bm0 + r) * K + s * 32 + c);
            }
#pragma unroll
            for (int i = 0; i < 4; i++) {
                int idx = tid + i * 256;
                int r = idx >> 5, c = (idx & 31) << 2;
                cp16(Bs + r * BS_STRIDE + c, W + (size_t)(s * 32 + r) * N + bn0 + c);
            }
        }
        asm volatile("cp.async.commit_group;\n");
    }

    for (int kt = 0; kt < ktiles; kt++) {
        asm volatile("cp.async.wait_group %0;\n" :: "n"(STAGES - 2));
        __syncthreads();

        // issue loads for tile kt+STAGES-1 into the buffer freed by tile kt-1
        int nk = kt + STAGES - 1;
        if (nk < ktiles) {
            float* As = smem + (nk % STAGES) * STAGE_FLOATS;
            float* Bs = As + 128 * AS_STRIDE;
#pragma unroll
            for (int i = 0; i < 4; i++) {
                int idx = tid + i * 256;
                int r = idx >> 3, c = (idx & 7) << 2;
                cp16(As + r * AS_STRIDE + c, A + (size_t)(bm0 + r) * K + nk * 32 + c);
            }
#pragma unroll
            for (int i = 0; i < 4; i++) {
                int idx = tid + i * 256;
                int r = idx >> 5, c = (idx & 31) << 2;
                cp16(Bs + r * BS_STRIDE + c, W + (size_t)(nk * 32 + r) * N + bn0 + c);
            }
        }
        asm volatile("cp.async.commit_group;\n");

        const float* As = smem + (kt % STAGES) * STAGE_FLOATS;
        const float* Bs = As + 128 * AS_STRIDE;
#pragma unroll
        for (int kk = 0; kk < 32; kk += 8) {
            wmma::fragment<wmma::matrix_a, 16, 16, 8, wmma::precision::tf32, wmma::row_major> af[4];
            wmma::fragment<wmma::matrix_b, 16, 16, 8, wmma::precision::tf32, wmma::row_major> bf[2];
#pragma unroll
            for (int i = 0; i < 4; i++)
                wmma::load_matrix_sync(af[i], As + (wm0 + i * 16) * AS_STRIDE + kk, AS_STRIDE);
#pragma unroll
            for (int j = 0; j < 2; j++)
                wmma::load_matrix_sync(bf[j], Bs + kk * BS_STRIDE + wn0 + j * 16, BS_STRIDE);
#pragma unroll
            for (int i = 0; i < 4; i++)
#pragma unroll
                for (int j = 0; j < 2; j++)
                    wmma::mma_sync(acc[i][j], af[i], bf[j], acc[i][j]);
        }
    }

    // ---- epilogue: park tile in smem, then coalesced float4 epilogue ----
    asm volatile("cp.async.wait_group 0;\n");
    __syncthreads();
    float* Cs = smem;   // 128 x BS_STRIDE
#pragma unroll
    for (int i = 0; i < 4; i++)
#pragma unroll
        for (int j = 0; j < 2; j++)
            wmma::store_matrix_sync(Cs + (wm0 + i * 16) * BS_STRIDE + wn0 + j * 16,
                                    acc[i][j], BS_STRIDE, wmma::mem_row_major);
    __syncthreads();

#pragma unroll
    for (int it = 0; it < 16; it++) {
        int idx = tid + it * 256;            // 0..4095
        int r = idx >> 5, c4 = (idx & 31) << 2;
        float4 v = *reinterpret_cast<float4*>(Cs + r * BS_STRIDE + c4);
        const int gc = bn0 + c4;
        const size_t go = (size_t)(bm0 + r) * N + gc;
        const float4 bv = *reinterpret_cast<const float4*>(bias + gc);
        v.x += bv.x; v.y += bv.y; v.z += bv.z; v.w += bv.w;
        if (EPI == EPI_SILU) {
            v.x = v.x / (1.0f + expf(-v.x));
            v.y = v.y / (1.0f + expf(-v.y));
            v.z = v.z / (1.0f + expf(-v.z));
            v.w = v.w / (1.0f + expf(-v.w));
        } else if (EPI == EPI_GATE) {
            const float4 gv = *reinterpret_cast<const float4*>(gate + go);
            const float4 rv = *reinterpret_cast<const float4*>(resid + go);
            v.x = gv.x * (v.x / (1.0f + expf(-v.x))) + rv.x;
            v.y = gv.y * (v.y / (1.0f + expf(-v.y))) + rv.y;
            v.z = gv.z * (v.z / (1.0f + expf(-v.z))) + rv.z;
            v.w = gv.w * (v.w / (1.0f + expf(-v.w))) + rv.w;
        } else {
            const float4 rv = *reinterpret_cast<const float4*>(resid + go);
            v.x += rv.x; v.y += rv.y; v.z += rv.z; v.w += rv.w;
        }
        *reinterpret_cast<float4*>(out + go) = v;
    }
}

// ---------------- launch ----------------------------------------------------
extern "C" void kernel_launch(void* const* d_in, const int* in_sizes, int n_in,
                              void* d_out, int out_size) {
    (void)in_sizes; (void)n_in; (void)out_size;
    const float* x     = (const float*)d_in[0];
    const float* lng   = (const float*)d_in[1];
    const float* lnb   = (const float*)d_in[2];
    const float* fcw   = (const float*)d_in[3];
    const float* fcb   = (const float*)d_in[4];
    const float* w1    = (const float*)d_in[5];
    const float* b1    = (const float*)d_in[6];
    const float* w2    = (const float*)d_in[7];
    const float* b2    = (const float*)d_in[8];
    const float* phre  = (const float*)d_in[9];
    const float* phim  = (const float*)d_in[10];
    const float* phire = (const float*)d_in[11];
    const float* phiim = (const float*)d_in[12];
    const float* lcre  = (const float*)d_in[13];
    const float* lcim  = (const float*)d_in[14];

    float *xn, *conv, *x3, *tb;
    cudaGetSymbolAddress((void**)&xn,   g_xn);
    cudaGetSymbolAddress((void**)&conv, g_conv);
    cudaGetSymbolAddress((void**)&x3,   g_x3);
    cudaGetSymbolAddress((void**)&tb,   g_t);
    float* x2 = (float*)d_out;   // d_out doubles as x2 buffer

    static bool attr_done = false;
    if (!attr_done) {
        cudaFuncSetAttribute(gemm_pipe<EPI_GATE>, cudaFuncAttributeMaxDynamicSharedMemorySize, GEMM_SMEM_BYTES);
        cudaFuncSetAttribute(gemm_pipe<EPI_SILU>, cudaFuncAttributeMaxDynamicSharedMemorySize, GEMM_SMEM_BYTES);
        cudaFuncSetAttribute(gemm_pipe<EPI_ADD>,  cudaFuncAttributeMaxDynamicSharedMemorySize, GEMM_SMEM_BYTES);
        attr_done = true;
    }

    const int M = BB * LL;

    ln_kernel<<<M, 256>>>(x, lng, lnb, xn);
    conv_a<<<dim3(DD / 256, CCH, BB), 256>>>(xn, phre, phim);
    conv_b<<<(BB * DD) / 256, 256>>>(phre, phim);
    conv_c<<<dim3(DD / 256, CCH, BB), 256>>>(xn, phre, phim, phire, phiim, lcre, lcim);

    // x2 = conv * silu(x @ fc_w + fc_b) + x
    gemm_pipe<EPI_GATE><<<dim3(DD / 128, M / 128), 256, GEMM_SMEM_BYTES>>>(x, fcw, fcb, conv, x, x2, M, DD, DD);
    // x3 = LN(x2)
    ln_kernel<<<M, 256>>>(x2, lng, lnb, x3);
    // t = silu(x3 @ w1 + b1)
    gemm_pipe<EPI_SILU><<<dim3(FFD / 128, M / 128), 256, GEMM_SMEM_BYTES>>>(x3, w1, b1, nullptr, nullptr, tb, M, FFD, DD);
    // out = x2 + t @ w2 + b2
    gemm_pipe<EPI_ADD><<<dim3(DD / 128, M / 128), 256, GEMM_SMEM_BYTES>>>(tb, w2, b2, nullptr, x2, x2, M, DD, FFD);
}